// round 16
// baseline (speedup 1.0000x reference)
#include <cuda_runtime.h>
#include <math.h>

#define NPOINTS 100000
#define BATCH   4096
#define KSEL    10
#define GRIDC   16
#define NCELLS  (GRIDC*GRIDC*GRIDC)
#define CHUNK   64
#define NCHUNK  1563                // ceil(100000/64)
#define NCHPAD  1568                // mult of 32
#define PTSPAD  (NCHUNK*CHUNK)     // 100032
#define FULLMASK 0xffffffffu
#define WPB     8
#define TPB     256
#define SEEDSTR 97                  // 1023*97 = 99231 < NPOINTS

// fixed grid bounds: data ~ N(0,0.1); cell_of clamps, so ANY bounds are correct.
#define GLO  (-0.75f)
#define GINV (GRIDC / 1.5f)

// ---- device scratch (static: no allocations) ----
__device__ int    g_cnt[NCELLS];
__device__ int    g_cur[NCELLS];
__device__ float4 g_pts[PTSPAD];     // (x,y,z,|p|^2) Morton-cell-sorted; pads w=+INF
__device__ int    g_sid[PTSPAD];
__device__ float4 g_cmeta[NCHPAD];   // chunk centroid (x,y,z,|c|^2); w=+INF if empty
__device__ float  g_crad[NCHPAD];

static __device__ __forceinline__ float sigmoidf_(float x) {
    return 1.0f / (1.0f + expf(-x));
}
// Morton (z-order) cell index: compact chunks -> small bounding radii
static __device__ __forceinline__ int cell_of(float x, float y, float z) {
    int ix = min(GRIDC-1, max(0, (int)((x - GLO) * GINV)));
    int iy = min(GRIDC-1, max(0, (int)((y - GLO) * GINV)));
    int iz = min(GRIDC-1, max(0, (int)((z - GLO) * GINV)));
    int m = 0;
    #pragma unroll
    for (int b = 0; b < 4; b++) {
        m |= ((ix >> b) & 1) << (3*b)
           | ((iy >> b) & 1) << (3*b + 1)
           | ((iz >> b) & 1) << (3*b + 2);
    }
    return m;
}

// lane-local sorted insert with index (ascending by key)
#define INSERT_L(kv, ki)                                                 \
    do { float _v = (kv); int _i = (ki);                                 \
        _Pragma("unroll")                                                \
        for (int _j = 0; _j < KSEL; _j++) {                              \
            if (_v < hd[_j]) {                                           \
                float _tv = hd[_j]; hd[_j] = _v; _v = _tv;               \
                int _ti = hix[_j]; hix[_j] = _i; _i = _ti;               \
            }                                                            \
        }                                                                \
    } while (0)

// lane-local sorted insert (values only)
#define SORT10_INS(arr, v)                                               \
    do { float _v = (v);                                                 \
        if (_v < arr[KSEL-1]) {                                          \
            _Pragma("unroll")                                            \
            for (int _j = 0; _j < KSEL; _j++) {                          \
                float _lo = fminf(arr[_j], _v);                          \
                float _hi = fmaxf(arr[_j], _v);                          \
                arr[_j] = _lo; _v = _hi;                                 \
            }                                                            \
        }                                                                \
    } while (0)

// ---------------------------------------------------------------------------
// Preprocessing (memset + 4 kernels) — unchanged from R13 (proven)
// ---------------------------------------------------------------------------
__global__ void pre_hist_kernel(const float* __restrict__ xyz) {
    int i = blockIdx.x * blockDim.x + threadIdx.x;
    if (i >= NPOINTS) return;
    atomicAdd(&g_cnt[cell_of(xyz[3*i], xyz[3*i+1], xyz[3*i+2])], 1);
}

__global__ __launch_bounds__(1024)
void pre_scan_kernel() {
    __shared__ int ssum[1024];
    int t = threadIdx.x;
    int v0 = g_cnt[t*4+0], v1 = g_cnt[t*4+1], v2 = g_cnt[t*4+2], v3 = g_cnt[t*4+3];
    int s = v0 + v1 + v2 + v3;
    ssum[t] = s;
    __syncthreads();
    for (int off = 1; off < 1024; off <<= 1) {
        int x = (t >= off) ? ssum[t - off] : 0;
        __syncthreads();
        ssum[t] += x;
        __syncthreads();
    }
    int excl = ssum[t] - s;
    g_cur[t*4+0] = excl;
    g_cur[t*4+1] = excl + v0;
    g_cur[t*4+2] = excl + v0 + v1;
    g_cur[t*4+3] = excl + v0 + v1 + v2;
}

__global__ void pre_scatter_kernel(const float* __restrict__ xyz) {
    int i = blockIdx.x * blockDim.x + threadIdx.x;
    if (i >= NPOINTS) return;
    float x = xyz[3*i], y = xyz[3*i+1], z = xyz[3*i+2];
    int pos = atomicAdd(&g_cur[cell_of(x, y, z)], 1);
    g_pts[pos] = make_float4(x, y, z, fmaf(x, x, fmaf(y, y, z*z)));
    g_sid[pos] = i;
}

__global__ void pre_chunkmeta_kernel() {
    int w    = (blockIdx.x * blockDim.x + threadIdx.x) >> 5;
    int lane = threadIdx.x & 31;
    if (w >= NCHPAD) return;
    const float POSINF = __int_as_float(0x7f800000);
    if (w >= NCHUNK) {
        if (lane == 0) { g_cmeta[w] = make_float4(0.f, 0.f, 0.f, POSINF); g_crad[w] = 0.f; }
        return;
    }
    int base = w * CHUNK;
    float4 v[2];
    #pragma unroll
    for (int i = 0; i < 2; i++) {
        int idx = base + i * 32 + lane;
        if (idx < NPOINTS) {
            v[i] = g_pts[idx];
        } else {
            v[i] = make_float4(0.f, 0.f, 0.f, POSINF);
            g_pts[idx] = v[i];
            g_sid[idx] = 0;
        }
    }
    int nreal = min(CHUNK, NPOINTS - base);
    float sx = 0.f, sy = 0.f, sz = 0.f;
    #pragma unroll
    for (int i = 0; i < 2; i++)
        if (base + i * 32 + lane < NPOINTS) { sx += v[i].x; sy += v[i].y; sz += v[i].z; }
    #pragma unroll
    for (int off = 16; off; off >>= 1) {
        sx += __shfl_xor_sync(FULLMASK, sx, off);
        sy += __shfl_xor_sync(FULLMASK, sy, off);
        sz += __shfl_xor_sync(FULLMASK, sz, off);
    }
    float inv = 1.0f / (float)nreal;
    float cx = sx * inv, cy = sy * inv, cz = sz * inv;
    float md = 0.f;
    #pragma unroll
    for (int i = 0; i < 2; i++) {
        if (base + i * 32 + lane < NPOINTS) {
            float ddx = v[i].x - cx, ddy = v[i].y - cy, ddz = v[i].z - cz;
            md = fmaxf(md, fmaf(ddx, ddx, fmaf(ddy, ddy, ddz * ddz)));
        }
    }
    #pragma unroll
    for (int off = 16; off; off >>= 1)
        md = fmaxf(md, __shfl_xor_sync(FULLMASK, md, off));
    if (lane == 0) {
        g_cmeta[w] = make_float4(cx, cy, cz, fmaf(cx, cx, fmaf(cy, cy, cz * cz)));
        g_crad[w] = sqrtf(md);
    }
}

// ---------------------------------------------------------------------------
// Main: one warp per ray; lane-local heaps, shfl-free hot loop, exact end merge
// ---------------------------------------------------------------------------
__global__ __launch_bounds__(TPB)
void gsplat_sweep_kernel(const float* __restrict__ rays_o,
                         const float* __restrict__ rays_d,
                         const float* __restrict__ fdc,
                         const float* __restrict__ opacity,
                         float* __restrict__ out)
{
    const int lane = threadIdx.x & 31;
    const int wid  = threadIdx.x >> 5;
    const int ray  = blockIdx.x * WPB + wid;
    const float POSINF = __int_as_float(0x7f800000);

    float ox = rays_o[3*ray+0], oy = rays_o[3*ray+1], oz = rays_o[3*ray+2];
    float dx = rays_d[3*ray+0], dy = rays_d[3*ray+1], dz = rays_d[3*ray+2];
    float cx = fmaf(dx, 3.0f, ox), cy = fmaf(dy, 3.0f, oy), cz = fmaf(dz, 3.0f, oz);
    float ax = -2.0f*cx, ay = -2.0f*cy, az = -2.0f*cz;
    float cn2 = cx*cx + cy*cy + cz*cz;

    // ---- seed thr_s: exact sample-10th over 1024 strided points (thr-only) ----
    float sa[KSEL];
    #pragma unroll
    for (int j = 0; j < KSEL; j++) sa[j] = POSINF;
    for (int ob = 0; ob < 8; ob++) {
        float4 q[4];
        #pragma unroll
        for (int ii = 0; ii < 4; ii++)
            q[ii] = __ldg(&g_pts[((ob * 4 + ii) * 32 + lane) * SEEDSTR]);
        #pragma unroll
        for (int ii = 0; ii < 4; ii++) {
            float k = fmaf(q[ii].x, ax, fmaf(q[ii].y, ay, fmaf(q[ii].z, az, q[ii].w)));
            SORT10_INS(sa, k);
        }
    }
    float thr_s;
    {
        float m = 0.f;
        #pragma unroll
        for (int rnd = 0; rnd < KSEL; rnd++) {
            float h = sa[0];
            #pragma unroll
            for (int off = 16; off; off >>= 1)
                h = fminf(h, __shfl_xor_sync(FULLMASK, h, off));
            m = h;
            bool c = (sa[0] == h);
            #pragma unroll
            for (int j = 0; j < KSEL-1; j++) sa[j] = c ? sa[j+1] : sa[j];
            if (c) sa[KSEL-1] = POSINF;
        }
        thr_s = m;                   // >= overall 10th (sample superset bound)
    }

    // lane-local heap (ascending); any overall-top-10 point always inserts:
    // if key >= lane_10th, that lane already holds 10 better points.
    float hd[KSEL]; int hix[KSEL];
    #pragma unroll
    for (int j = 0; j < KSEL; j++) { hd[j] = POSINF; hix[j] = 0; }
    float thr_g = thr_s;             // lane insert guard = min(lane_10th, thr_s)
    float t2 = 2.0f * sqrtf(fmaxf(thr_s + cn2, 0.0f));

    // ---- screened linear sweep; NO warp sync in the candidate path ----
    for (int cb = 0; cb < NCHPAD; cb += 32) {
        float4 m  = __ldg(&g_cmeta[cb + lane]);
        float rad = __ldg(&g_crad[cb + lane]);
        float kc  = fmaf(m.x, ax, fmaf(m.y, ay, fmaf(m.z, az, m.w)));
        bool pass = kc <= thr_s + fmaf(t2, rad, rad * rad);
        unsigned pm = __ballot_sync(FULLMASK, pass);
        while (pm) {
            int src = __ffs(pm) - 1;
            pm &= pm - 1;
            int pb = (cb + src) * CHUNK;
            float4 q0 = __ldg(&g_pts[pb + lane]);
            float4 q1 = __ldg(&g_pts[pb + 32 + lane]);
            float k0 = fmaf(q0.x, ax, fmaf(q0.y, ay, fmaf(q0.z, az, q0.w)));
            float k1 = fmaf(q1.x, ax, fmaf(q1.y, ay, fmaf(q1.z, az, q1.w)));
            if (k0 <= thr_g) {       // SIMT: body runs once for all inserting lanes
                INSERT_L(k0, pb + lane);
                thr_g = fminf(hd[KSEL-1], thr_s);
            }
            if (k1 <= thr_g) {
                INSERT_L(k1, pb + 32 + lane);
                thr_g = fminf(hd[KSEL-1], thr_s);
            }
        }
        // refresh shared screening threshold: warp-min of lane guards
        float t = thr_g;
        #pragma unroll
        for (int off = 16; off; off >>= 1)
            t = fminf(t, __shfl_xor_sync(FULLMASK, t, off));
        thr_s = fminf(thr_s, t);
        thr_g = fminf(thr_g, thr_s);
        t2 = 2.0f * sqrtf(fmaxf(thr_s + cn2, 0.0f));
    }

    // ---- exact merge of 32 lane-local top-10s + fused epilogue ----
    float ws = 0.f, e0 = 0.f, e1 = 0.f, e2 = 0.f;
    #pragma unroll
    for (int rnd = 0; rnd < KSEL; rnd++) {
        float h = hd[0];
        #pragma unroll
        for (int off = 16; off; off >>= 1)
            h = fminf(h, __shfl_xor_sync(FULLMASK, h, off));
        unsigned sel = __ballot_sync(FULLMASK, hd[0] == h);
        int src = __ffs(sel) - 1;
        int pidx = __shfl_sync(FULLMASK, hix[0], src);
        if (lane == src) {           // pop the winning lane's head
            #pragma unroll
            for (int j = 0; j < KSEL-1; j++) { hd[j] = hd[j+1]; hix[j] = hix[j+1]; }
            hd[KSEL-1] = POSINF;
        }
        // epilogue accumulation (identical in all lanes; warp-uniform loads)
        float dist = sqrtf(fmaxf(h + cn2, 0.0f));
        int id = __ldg(&g_sid[pidx]);
        float w = expf(-0.1f * dist) * sigmoidf_(__ldg(&opacity[id]));
        ws += w;
        e0 = fmaf(w, sigmoidf_(__ldg(&fdc[3*id+0])), e0);
        e1 = fmaf(w, sigmoidf_(__ldg(&fdc[3*id+1])), e1);
        e2 = fmaf(w, sigmoidf_(__ldg(&fdc[3*id+2])), e2);
    }
    if (lane == 0) {
        float inv = 1.0f / (ws + 1e-8f);
        out[3*ray+0] = e0 * inv;
        out[3*ray+1] = e1 * inv;
        out[3*ray+2] = e2 * inv;
    }
}

extern "C" void kernel_launch(void* const* d_in, const int* in_sizes, int n_in,
                              void* d_out, int out_size)
{
    const float* rays_o  = (const float*)d_in[0];
    const float* rays_d  = (const float*)d_in[1];
    const float* xyz     = (const float*)d_in[2];
    const float* fdc     = (const float*)d_in[3];
    const float* opacity = (const float*)d_in[4];
    float* out = (float*)d_out;

    void* cnt_addr = nullptr;
    cudaGetSymbolAddress(&cnt_addr, g_cnt);
    cudaMemsetAsync(cnt_addr, 0, NCELLS * sizeof(int));

    const int PB = (NPOINTS + 1023) / 1024;
    pre_hist_kernel<<<PB, 1024>>>(xyz);
    pre_scan_kernel<<<1, 1024>>>();
    pre_scatter_kernel<<<PB, 1024>>>(xyz);
    pre_chunkmeta_kernel<<<(NCHPAD * 32) / TPB, TPB>>>();
    gsplat_sweep_kernel<<<BATCH / WPB, TPB>>>(
        rays_o, rays_d, fdc, opacity, out);
}